// round 16
// baseline (speedup 1.0000x reference)
#include <cuda_runtime.h>

// Problem constants
#define BB   2
#define SS   2048
#define DD   1024
#define HH   16
#define DH   64
#define MM   (BB*SS)          // 4096 rows

// -------- scratch (device globals: allocation-free contract) --------
__device__ float g_Q[4194304];   // [MM, DD] 16MB
__device__ float g_K[4194304];
__device__ float g_V[4194304];
__device__ float g_O[4194304];   // attention output, [B,S,D] layout

// ============================================================================
// GEMM: C[M,N] = A[M,K] * B[N,K]^T + bias[N]   (both operands K-contiguous)
// 128x128 tile, TK=8, 256 threads, 8x8 per-thread micro tile, double buffered
// ============================================================================
__global__ void __launch_bounds__(256) gemm_bias_nt(
    const float* __restrict__ A,
    const float* __restrict__ Bw,
    const float* __restrict__ bias,
    float* __restrict__ C,
    int M, int N, int K)
{
    __shared__ float As[2][8][132];
    __shared__ float Bs[2][8][132];

    const int t  = threadIdx.x;
    const int tx = t & 15;
    const int ty = t >> 4;
    const int bm = blockIdx.y * 128;
    const int bn = blockIdx.x * 128;

    const int lrow = t >> 1;          // 0..127
    const int lk   = (t & 1) * 4;     // 0 or 4

    const float* Ap = A  + (size_t)(bm + lrow) * K + lk;
    const float* Bp = Bw + (size_t)(bn + lrow) * K + lk;

    float c[8][8];
#pragma unroll
    for (int i = 0; i < 8; i++)
#pragma unroll
        for (int j = 0; j < 8; j++) c[i][j] = 0.f;

    float4 av = *(const float4*)Ap;
    float4 bv = *(const float4*)Bp;

    As[0][lk+0][lrow]=av.x; As[0][lk+1][lrow]=av.y; As[0][lk+2][lrow]=av.z; As[0][lk+3][lrow]=av.w;
    Bs[0][lk+0][lrow]=bv.x; Bs[0][lk+1][lrow]=bv.y; Bs[0][lk+2][lrow]=bv.z; Bs[0][lk+3][lrow]=bv.w;
    __syncthreads();

    const int nk = K >> 3;
    int buf = 0;
    for (int kt = 0; kt < nk; kt++) {
        if (kt + 1 < nk) {
            av = *(const float4*)(Ap + (kt + 1) * 8);
            bv = *(const float4*)(Bp + (kt + 1) * 8);
        }
#pragma unroll
        for (int k = 0; k < 8; k++) {
            float a[8], b[8];
            *(float4*)&a[0] = *(const float4*)&As[buf][k][ty*4];
            *(float4*)&a[4] = *(const float4*)&As[buf][k][ty*4 + 64];
            *(float4*)&b[0] = *(const float4*)&Bs[buf][k][tx*4];
            *(float4*)&b[4] = *(const float4*)&Bs[buf][k][tx*4 + 64];
#pragma unroll
            for (int i = 0; i < 8; i++)
#pragma unroll
                for (int j = 0; j < 8; j++)
                    c[i][j] += a[i] * b[j];
        }
        if (kt + 1 < nk) {
            buf ^= 1;
            As[buf][lk+0][lrow]=av.x; As[buf][lk+1][lrow]=av.y; As[buf][lk+2][lrow]=av.z; As[buf][lk+3][lrow]=av.w;
            Bs[buf][lk+0][lrow]=bv.x; Bs[buf][lk+1][lrow]=bv.y; Bs[buf][lk+2][lrow]=bv.z; Bs[buf][lk+3][lrow]=bv.w;
            __syncthreads();
        }
    }

    // epilogue: += bias, float4 stores
#pragma unroll
    for (int ih = 0; ih < 2; ih++) {
#pragma unroll
        for (int i = 0; i < 4; i++) {
            int row = bm + ih*64 + ty*4 + i;
#pragma unroll
            for (int jh = 0; jh < 2; jh++) {
                int col = bn + jh*64 + tx*4;
                float4 bb = *(const float4*)(bias + col);
                float4 o;
                o.x = c[ih*4+i][jh*4+0] + bb.x;
                o.y = c[ih*4+i][jh*4+1] + bb.y;
                o.z = c[ih*4+i][jh*4+2] + bb.z;
                o.w = c[ih*4+i][jh*4+3] + bb.w;
                *(float4*)(C + (size_t)row * N + col) = o;
            }
        }
    }
}

// ============================================================================
// Fused attention: per CTA = one (b, h, 16-row q tile).
// Full score rows kept in smem -> exact single-pass softmax, attn written once.
// ============================================================================
#define QT        16
#define JC        128
#define SC_STRIDE 2052    // 2048 + 4 pad (bank-conflict free across q rows)

__global__ void __launch_bounds__(256) attn_fused(
    const float* __restrict__ Q,
    const float* __restrict__ K,
    const float* __restrict__ V,
    float* __restrict__ attn,     // may be null (then attn not materialized)
    float* __restrict__ O)
{
    extern __shared__ float sm[];
    float* sc   = sm;                          // [QT][SC_STRIDE]
    float* Ks   = sc + QT * SC_STRIDE;         // [JC][65]
    float* Vs   = Ks + JC * 65;                // [JC][68]
    float* Qs   = Vs + JC * 68;                // [QT][64]
    float* rinv = Qs + QT * 64;                // [QT]

    const int t  = threadIdx.x;
    const int q0 = blockIdx.x * QT;
    const int h  = blockIdx.y;
    const int b  = blockIdx.z;
    const size_t base = (size_t)b * SS * DD + (size_t)h * DH;

    // ---- load Q tile (16x64) ----
    {
        int row = t >> 4, f4 = t & 15;
        float4 v = *(const float4*)(Q + base + (size_t)(q0 + row) * DD + f4 * 4);
        *(float4*)(Qs + row * 64 + f4 * 4) = v;
    }
    __syncthreads();

    const int qi = t >> 4;    // q-row owned by this thread (0..15)
    const int jg = t & 15;    // column group
    const int d4 = t & 15;    // staging: float4 index along DH
    const int j0 = t >> 4;    // staging: base key row

    // Q row into registers (reused for all 16 key chunks)
    float qreg[DH];
#pragma unroll
    for (int d = 0; d < DH; d++) qreg[d] = Qs[qi * 64 + d];

    // ---- QK^T phase: scores into smem ----
    for (int c = 0; c < SS / JC; c++) {
#pragma unroll
        for (int jj = 0; jj < 8; jj++) {
            int j = j0 + jj * 16;
            float4 v = *(const float4*)(K + base + (size_t)(c * JC + j) * DD + d4 * 4);
            Ks[j*65 + d4*4 + 0] = v.x;
            Ks[j*65 + d4*4 + 1] = v.y;
            Ks[j*65 + d4*4 + 2] = v.z;
            Ks[j*65 + d4*4 + 3] = v.w;
        }
        __syncthreads();

        float acc[8] = {0.f,0.f,0.f,0.f,0.f,0.f,0.f,0.f};
#pragma unroll
        for (int d = 0; d < DH; d++) {
            float qv = qreg[d];
#pragma unroll
            for (int jj = 0; jj < 8; jj++)
                acc[jj] += qv * Ks[(jg + jj * 16) * 65 + d];
        }
#pragma unroll
        for (int jj = 0; jj < 8; jj++)
            sc[qi * SC_STRIDE + c * JC + jg + jj * 16] = acc[jj];
        __syncthreads();
    }

    // ---- softmax (exact, max-subtract) + attn store ----
    const int warp = t >> 5, lane = t & 31;
    const float sscale = 0.125f;   // 1/sqrt(64)
    for (int r = warp; r < QT; r += 8) {
        float* row = sc + r * SC_STRIDE;
        float mx = -1e30f;
        for (int j = lane; j < SS; j += 32) mx = fmaxf(mx, row[j]);
#pragma unroll
        for (int o = 16; o > 0; o >>= 1) mx = fmaxf(mx, __shfl_xor_sync(0xffffffffu, mx, o));
        float sum = 0.f;
        for (int j = lane; j < SS; j += 32) {
            float e = __expf((row[j] - mx) * sscale);
            row[j] = e;
            sum += e;
        }
#pragma unroll
        for (int o = 16; o > 0; o >>= 1) sum += __shfl_xor_sync(0xffffffffu, sum, o);
        float ri = 1.f / sum;
        if (lane == 0) rinv[r] = ri;

        if (attn) {
            float4* dst = (float4*)(attn + ((((size_t)b * HH + h) * SS) + (q0 + r)) * SS);
            const float4* src = (const float4*)row;
            for (int j4 = lane; j4 < SS / 4; j4 += 32) {
                float4 e4 = src[j4];
                e4.x *= ri; e4.y *= ri; e4.z *= ri; e4.w *= ri;
                dst[j4] = e4;
            }
        }
    }
    __syncthreads();

    // ---- PV phase: out[qi, d] = (sum_j e * v) * rinv ----
    float o0 = 0.f, o1 = 0.f, o2 = 0.f, o3 = 0.f;
    for (int c = 0; c < SS / JC; c++) {
#pragma unroll
        for (int jj = 0; jj < 8; jj++) {
            int j = j0 + jj * 16;
            float4 v = *(const float4*)(V + base + (size_t)(c * JC + j) * DD + d4 * 4);
            *(float4*)(Vs + j * 68 + d4 * 4) = v;
        }
        __syncthreads();
#pragma unroll 4
        for (int j = 0; j < JC; j++) {
            float p = sc[qi * SC_STRIDE + c * JC + j];
            float4 vv = *(const float4*)(Vs + j * 68 + jg * 4);
            o0 += p * vv.x; o1 += p * vv.y; o2 += p * vv.z; o3 += p * vv.w;
        }
        __syncthreads();
    }
    float ri = rinv[qi];
    float4 o4 = make_float4(o0 * ri, o1 * ri, o2 * ri, o3 * ri);
    // O in [B,S,D] layout (head-interleaved) so the final GEMM consumes it directly
    *(float4*)(O + base + (size_t)(q0 + qi) * DD + jg * 4) = o4;
}

// ============================================================================
extern "C" void kernel_launch(void* const* d_in, const int* in_sizes, int n_in,
                              void* d_out, int out_size)
{
    const float* query = (const float*)d_in[0];
    const float* key   = (const float*)d_in[1];
    const float* value = (const float*)d_in[2];
    const float* Wq = (const float*)d_in[3];
    const float* bq = (const float*)d_in[4];
    const float* Wk = (const float*)d_in[5];
    const float* bk = (const float*)d_in[6];
    const float* Wv = (const float*)d_in[7];
    const float* bv = (const float*)d_in[8];
    const float* Wo = (const float*)d_in[9];
    const float* bo = (const float*)d_in[10];

    float* out = (float*)d_out;
    const long long OUT_ELEMS  = (long long)MM * DD;                 // 4,194,304
    const long long ATTN_ELEMS = (long long)BB * HH * SS * (long long)SS;
    float* attn = nullptr;
    if ((long long)out_size >= OUT_ELEMS + ATTN_ELEMS)
        attn = out + OUT_ELEMS;   // tuple flatten order: (out, attn)

    float *pQ, *pK, *pV, *pO;
    cudaGetSymbolAddress((void**)&pQ, g_Q);
    cudaGetSymbolAddress((void**)&pK, g_K);
    cudaGetSymbolAddress((void**)&pV, g_V);
    cudaGetSymbolAddress((void**)&pO, g_O);

    const int smem_bytes = (QT * SC_STRIDE + JC * 65 + JC * 68 + QT * 64 + QT) * 4;
    cudaFuncSetAttribute(attn_fused, cudaFuncAttributeMaxDynamicSharedMemorySize, smem_bytes);

    dim3 gg(DD / 128, MM / 128);   // (8, 32)

    gemm_bias_nt<<<gg, 256>>>(query, Wq, bq, pQ, MM, DD, DD);
    gemm_bias_nt<<<gg, 256>>>(key,   Wk, bk, pK, MM, DD, DD);
    gemm_bias_nt<<<gg, 256>>>(value, Wv, bv, pV, MM, DD, DD);

    attn_fused<<<dim3(SS / QT, HH, BB), 256, smem_bytes>>>(pQ, pK, pV, attn, pO);

    gemm_bias_nt<<<gg, 256>>>(pO, Wo, bo, out, MM, DD, DD);
}